// round 1
// baseline (speedup 1.0000x reference)
#include <cuda_runtime.h>
#include <math.h>

#define NTOK 64
#define CDIM 256
#define C2   128
#define NHEADS 8
#define HD   32
#define QS   260          // padded row stride (floats) for q/k/v smem; 260*4 % 16 == 0
#define NWIN 64
#define NBATCH 2048

// SMEM: q,k,v (64 x 260 each) + x branch tile (64 x 128) = 58112 floats = 232448 B = 227 KB
#define SMEM_FLOATS (3*NTOK*QS + NTOK*C2)
#define SMEM_BYTES  (SMEM_FLOATS * 4)

__device__ float d_tbl2[225 * NHEADS];                 // CPB-MLP output per table row
__device__ float d_biasS[NHEADS * NTOK * NTOK];        // 16*sigmoid(bias)[h][i][j]

// ---------------- prologue 1: rpb_table -> MLP -> (225, 8) ----------------
__global__ void cpb_mlp_kernel(const float* __restrict__ rpb,
                               const float* __restrict__ w1,
                               const float* __restrict__ b1,
                               const float* __restrict__ w2) {
    int p = threadIdx.x;
    if (p >= 225) return;
    float t0 = rpb[p * 2 + 0];
    float t1 = rpb[p * 2 + 1];
    float acc[NHEADS];
#pragma unroll
    for (int h = 0; h < NHEADS; ++h) acc[h] = 0.f;
    for (int j = 0; j < 128; ++j) {
        float hid = t0 * w1[j] + t1 * w1[128 + j] + b1[j];
        hid = fmaxf(hid, 0.f);
#pragma unroll
        for (int h = 0; h < NHEADS; ++h) acc[h] = fmaf(hid, w2[j * 8 + h], acc[h]);
    }
#pragma unroll
    for (int h = 0; h < NHEADS; ++h) d_tbl2[p * 8 + h] = acc[h];
}

// ---------------- prologue 2: gather + 16*sigmoid -> (8, 64, 64) ----------------
__global__ void bias_gather_kernel(const int* __restrict__ rpi) {
    int idx = blockIdx.x * blockDim.x + threadIdx.x;
    if (idx >= NHEADS * NTOK * NTOK) return;
    int h  = idx >> 12;       // / 4096
    int ij = idx & 4095;
    float bv = d_tbl2[rpi[ij] * 8 + h];
    d_biasS[idx] = 16.f / (1.f + expf(-bv));
}

// ---------------- main fused kernel: one CTA per window ----------------
__global__ void __launch_bounds__(256, 1)
swin_block_kernel(const float* __restrict__ x,  const float* __restrict__ mask,
                  const float* __restrict__ qw, const float* __restrict__ qb,
                  const float* __restrict__ kw, const float* __restrict__ kb,
                  const float* __restrict__ vw, const float* __restrict__ vb,
                  const float* __restrict__ pw, const float* __restrict__ pb,
                  const float* __restrict__ ls, float* __restrict__ out)
{
    extern __shared__ float sm[];
    float* qs = sm;
    float* kss = sm + NTOK * QS;
    float* vss = sm + 2 * NTOK * QS;
    float* xs  = sm + 3 * NTOK * QS;      // 64 x 128 (current branch)

    const int b   = blockIdx.x;
    const int tid = threadIdx.x;
    const int rg  = tid >> 6;             // 0..3  -> 16 rows each
    const int cg  = tid & 63;             // 0..63
    const int i0  = rg * 16;

    const float* xg = x + (size_t)b * (NTOK * CDIM);

    // =========== Phase 1: QKV dual-branch residual linears ===========
    for (int s = 0; s < 2; ++s) {
        // load x branch tile (64 x 128) into smem, coalesced float4
        {
            const float4* src = (const float4*)xg;
            float4* dst = (float4*)xs;
            for (int t = tid; t < NTOK * 32; t += 256) {
                int i = t >> 5, c4 = t & 31;
                dst[i * 32 + c4] = src[i * 64 + s * 32 + c4];
            }
        }
        __syncthreads();

        float aq[32], ak[32], av[32];
#pragma unroll
        for (int r = 0; r < 32; ++r) { aq[r] = 0.f; ak[r] = 0.f; av[r] = 0.f; }

        const float* qwp = qw + s * 16384 + cg * 2;
        const float* kwp = kw + s * 16384 + cg * 2;
        const float* vwp = vw + s * 16384 + cg * 2;

        for (int c = 0; c < 128; c += 2) {
            float2 xv[16];
#pragma unroll
            for (int r = 0; r < 16; ++r)
                xv[r] = *(const float2*)&xs[(i0 + r) * 128 + c];
#pragma unroll
            for (int u = 0; u < 2; ++u) {
                float2 w0 = *(const float2*)(qwp + (c + u) * 128);
                float2 w1v = *(const float2*)(kwp + (c + u) * 128);
                float2 w2v = *(const float2*)(vwp + (c + u) * 128);
#pragma unroll
                for (int r = 0; r < 16; ++r) {
                    float xu = (&xv[r].x)[u];
                    aq[r * 2 + 0] = fmaf(xu, w0.x,  aq[r * 2 + 0]);
                    aq[r * 2 + 1] = fmaf(xu, w0.y,  aq[r * 2 + 1]);
                    ak[r * 2 + 0] = fmaf(xu, w1v.x, ak[r * 2 + 0]);
                    ak[r * 2 + 1] = fmaf(xu, w1v.y, ak[r * 2 + 1]);
                    av[r * 2 + 0] = fmaf(xu, w2v.x, av[r * 2 + 0]);
                    av[r * 2 + 1] = fmaf(xu, w2v.y, av[r * 2 + 1]);
                }
            }
        }

        // epilogue: residual + bias -> q/k/v smem
        {
            int d = cg * 2;
            float qb0 = qb[s * 128 + d], qb1 = qb[s * 128 + d + 1];
            float kb0 = kb[s * 128 + d], kb1 = kb[s * 128 + d + 1];
            float vb0 = vb[s * 128 + d], vb1 = vb[s * 128 + d + 1];
#pragma unroll
            for (int r = 0; r < 16; ++r) {
                int i = i0 + r;
                float x0 = xs[i * 128 + d];
                float x1 = xs[i * 128 + d + 1];
                int o = i * QS + s * 128 + d;
                qs[o]      = x0 + aq[r * 2 + 0] + qb0;
                qs[o + 1]  = x1 + aq[r * 2 + 1] + qb1;
                kss[o]     = x0 + ak[r * 2 + 0] + kb0;
                kss[o + 1] = x1 + ak[r * 2 + 1] + kb1;
                vss[o]     = x0 + av[r * 2 + 0] + vb0;
                vss[o + 1] = x1 + av[r * 2 + 1] + vb1;
            }
        }
        __syncthreads();
    }

    // =========== Phase 2: l2-normalize q,k per (head,row); fold logit scale into q ===========
#pragma unroll
    for (int t4 = 0; t4 < 4; ++t4) {
        int t = tid + t4 * 256;          // 1024 tasks: {q,k} x 8 heads x 64 rows
        int bufsel = t >> 9;
        int h = (t >> 6) & 7;
        int i = t & 63;
        float* base = (bufsel ? kss : qs) + i * QS + h * HD;
        float4 vv[8];
        float ssq = 0.f;
#pragma unroll
        for (int u = 0; u < 8; ++u) {
            vv[u] = ((float4*)base)[u];
            ssq = fmaf(vv[u].x, vv[u].x, ssq);
            ssq = fmaf(vv[u].y, vv[u].y, ssq);
            ssq = fmaf(vv[u].z, vv[u].z, ssq);
            ssq = fmaf(vv[u].w, vv[u].w, ssq);
        }
        float inv = 1.f / fmaxf(sqrtf(ssq), 1e-12f);
        if (bufsel == 0) inv *= fminf(expf(ls[h]), 100.f);   // exp(min(ls, log 100))
#pragma unroll
        for (int u = 0; u < 8; ++u) {
            vv[u].x *= inv; vv[u].y *= inv; vv[u].z *= inv; vv[u].w *= inv;
            ((float4*)base)[u] = vv[u];
        }
    }
    __syncthreads();

    // =========== Phase 3: attention (per (head,row) fully in registers) ===========
    const float* maskw = mask + (size_t)(b & (NWIN - 1)) * (NTOK * NTOK);
#pragma unroll 1
    for (int rr = 0; rr < 2; ++rr) {
        int row = tid + rr * 256;        // 512 rows = 8 heads x 64 tokens
        int h = row >> 6;
        int i = row & 63;

        const float4* qrow = (const float4*)(qs + i * QS + h * HD);
        float4 qv[8];
#pragma unroll
        for (int u = 0; u < 8; ++u) qv[u] = qrow[u];

        const float* bptr = d_biasS + h * 4096 + i * 64;
        const float* mptr = maskw + i * 64;

        float lg[64];
#pragma unroll
        for (int m = 0; m < 64; ++m) {
            const float4* krow = (const float4*)(kss + m * QS + h * HD);
            float dacc = 0.f;
#pragma unroll
            for (int u = 0; u < 8; ++u) {
                float4 kv = krow[u];
                dacc = fmaf(qv[u].x, kv.x, dacc);
                dacc = fmaf(qv[u].y, kv.y, dacc);
                dacc = fmaf(qv[u].z, kv.z, dacc);
                dacc = fmaf(qv[u].w, kv.w, dacc);
            }
            lg[m] = dacc + bptr[m] + mptr[m];
        }

        float mx = lg[0];
#pragma unroll
        for (int m = 1; m < 64; ++m) mx = fmaxf(mx, lg[m]);
        float ssum = 0.f;
#pragma unroll
        for (int m = 0; m < 64; ++m) { lg[m] = expf(lg[m] - mx); ssum += lg[m]; }
        float isum = 1.f / ssum;

        float4 oacc[8];
#pragma unroll
        for (int u = 0; u < 8; ++u) oacc[u] = make_float4(0.f, 0.f, 0.f, 0.f);
#pragma unroll
        for (int m = 0; m < 64; ++m) {
            const float4* vrow = (const float4*)(vss + m * QS + h * HD);
            float wv = lg[m];
#pragma unroll
            for (int u = 0; u < 8; ++u) {
                float4 vvv = vrow[u];
                oacc[u].x = fmaf(wv, vvv.x, oacc[u].x);
                oacc[u].y = fmaf(wv, vvv.y, oacc[u].y);
                oacc[u].z = fmaf(wv, vvv.z, oacc[u].z);
                oacc[u].w = fmaf(wv, vvv.w, oacc[u].w);
            }
        }
        // write attention output over this thread's own q row (exclusive ownership)
        float4* orow = (float4*)(qs + i * QS + h * HD);
#pragma unroll
        for (int u = 0; u < 8; ++u) {
            oacc[u].x *= isum; oacc[u].y *= isum; oacc[u].z *= isum; oacc[u].w *= isum;
            orow[u] = oacc[u];
        }
    }
    __syncthreads();

    // =========== Phase 4: output projection (no residual) ===========
    {
        int col0 = cg * 4;               // 0..252
        int s2   = col0 >> 7;            // branch
        int d0   = col0 & 127;
        const float* pwp = pw + s2 * 16384 + d0;

        float4 ac[16];
#pragma unroll
        for (int r = 0; r < 16; ++r) ac[r] = make_float4(0.f, 0.f, 0.f, 0.f);

        for (int c = 0; c < 128; c += 4) {
            float4 ov[16];
#pragma unroll
            for (int r = 0; r < 16; ++r)
                ov[r] = *(const float4*)&qs[(i0 + r) * QS + s2 * 128 + c];
#pragma unroll
            for (int u = 0; u < 4; ++u) {
                float4 wv = *(const float4*)(pwp + (c + u) * 128);
#pragma unroll
                for (int r = 0; r < 16; ++r) {
                    float o = (&ov[r].x)[u];
                    ac[r].x = fmaf(o, wv.x, ac[r].x);
                    ac[r].y = fmaf(o, wv.y, ac[r].y);
                    ac[r].z = fmaf(o, wv.z, ac[r].z);
                    ac[r].w = fmaf(o, wv.w, ac[r].w);
                }
            }
        }
        float4 pbv = *(const float4*)(pb + s2 * 128 + d0);
        float* og = out + (size_t)b * (NTOK * CDIM);
#pragma unroll
        for (int r = 0; r < 16; ++r) {
            float4 res;
            res.x = ac[r].x + pbv.x;
            res.y = ac[r].y + pbv.y;
            res.z = ac[r].z + pbv.z;
            res.w = ac[r].w + pbv.w;
            *(float4*)(og + (i0 + r) * 256 + col0) = res;
        }
    }
}

extern "C" void kernel_launch(void* const* d_in, const int* in_sizes, int n_in,
                              void* d_out, int out_size) {
    const float* x    = (const float*)d_in[0];
    const float* mask = (const float*)d_in[1];
    const float* qw   = (const float*)d_in[2];
    const float* qb   = (const float*)d_in[3];
    const float* kw   = (const float*)d_in[4];
    const float* kb   = (const float*)d_in[5];
    const float* vw   = (const float*)d_in[6];
    const float* vb   = (const float*)d_in[7];
    const float* pw   = (const float*)d_in[8];
    const float* pb   = (const float*)d_in[9];
    const float* w1   = (const float*)d_in[10];
    const float* b1   = (const float*)d_in[11];
    const float* w2   = (const float*)d_in[12];
    const float* ls   = (const float*)d_in[13];
    const float* rpb  = (const float*)d_in[14];
    const int*   rpi  = (const int*)d_in[15];
    float* out = (float*)d_out;

    // one-time opt-in to 227KB dynamic smem (done on the uncaptured correctness
    // call; attribute persists for the captured replays — work is identical every call)
    static bool inited = false;
    if (!inited) {
        cudaFuncSetAttribute(swin_block_kernel,
                             cudaFuncAttributeMaxDynamicSharedMemorySize, SMEM_BYTES);
        inited = true;
    }

    cpb_mlp_kernel<<<1, 256>>>(rpb, w1, b1, w2);
    bias_gather_kernel<<<(NHEADS * NTOK * NTOK + 255) / 256, 256>>>(rpi);
    swin_block_kernel<<<NBATCH, 256, SMEM_BYTES>>>(x, mask, qw, qb, kw, kb,
                                                   vw, vb, pw, pb, ls, out);
}

// round 2
// speedup vs baseline: 1.2794x; 1.2794x over previous
#include <cuda_runtime.h>
#include <math.h>
#include <stdint.h>

#define NTOK 64
#define CDIM 256
#define C2   128
#define NHEADS 8
#define HD   32
#define QS   260          // q/k row stride (floats): conflict-free mma A-frag loads
#define VSTR 256          // v row stride (floats): phase-3 reads are broadcast
#define WSS  132          // weight staging row stride
#define NWIN 64
#define NBATCH 2048

// smem layout (floats): qs[64][260] | ks[64][260] | vs[64][256] | Wst[64][132]
#define OFF_Q 0
#define OFF_K (64*QS)
#define OFF_V (2*64*QS)
#define OFF_W (2*64*QS + 64*VSTR)
#define SMEM_FLOATS (2*64*QS + 64*VSTR + 64*WSS)
#define SMEM_BYTES  (SMEM_FLOATS * 4)          // 232448 B == sm_103a cap

__device__ float d_tbl2[225 * NHEADS];
__device__ float d_biasS[NHEADS * NTOK * NTOK];

// ---------------- prologue 1: rpb_table -> MLP -> (225, 8), one block per p ----------------
__global__ void cpb_mlp_kernel(const float* __restrict__ rpb,
                               const float* __restrict__ w1,
                               const float* __restrict__ b1,
                               const float* __restrict__ w2) {
    __shared__ float acc[NHEADS];
    int p = blockIdx.x;          // 0..224
    int j = threadIdx.x;         // 0..127
    if (j < NHEADS) acc[j] = 0.f;
    __syncthreads();
    float t0 = rpb[p * 2 + 0];
    float t1 = rpb[p * 2 + 1];
    float hid = fmaxf(t0 * w1[j] + t1 * w1[128 + j] + b1[j], 0.f);
#pragma unroll
    for (int h = 0; h < NHEADS; ++h) {
        float pv = hid * w2[j * 8 + h];
#pragma unroll
        for (int o = 16; o; o >>= 1) pv += __shfl_xor_sync(0xffffffffu, pv, o);
        if ((j & 31) == 0) atomicAdd(&acc[h], pv);
    }
    __syncthreads();
    if (j < NHEADS) d_tbl2[p * 8 + j] = acc[j];
}

// ---------------- prologue 2: gather + 16*sigmoid -> (8, 64, 64) ----------------
__global__ void bias_gather_kernel(const int* __restrict__ rpi) {
    int idx = blockIdx.x * blockDim.x + threadIdx.x;
    if (idx >= NHEADS * NTOK * NTOK) return;
    int h  = idx >> 12;
    int ij = idx & 4095;
    float bv = d_tbl2[rpi[ij] * 8 + h];
    d_biasS[idx] = 16.f / (1.f + expf(-bv));
}

// ---------------- mma helpers ----------------
__device__ __forceinline__ void mma_tf32(float& d0, float& d1, float& d2, float& d3,
                                         uint32_t a0, uint32_t a1, uint32_t a2, uint32_t a3,
                                         uint32_t b0, uint32_t b1) {
    asm volatile(
        "mma.sync.aligned.m16n8k8.row.col.f32.tf32.tf32.f32 "
        "{%0,%1,%2,%3},{%4,%5,%6,%7},{%8,%9},{%0,%1,%2,%3};"
        : "+f"(d0), "+f"(d1), "+f"(d2), "+f"(d3)
        : "r"(a0), "r"(a1), "r"(a2), "r"(a3), "r"(b0), "r"(b1));
}
__device__ __forceinline__ uint32_t f2tf(float f) {
    uint32_t u; asm("cvt.rna.tf32.f32 %0, %1;" : "=r"(u) : "f"(f)); return u;
}

// stage W half [64][128] fp32 into Wst, then mma 8 k-tiles x 8 n-tiles into ACC
#define DO_GEMM(WPTR, ACC) do {                                              \
    __syncthreads();                                                         \
    for (int t = tid; t < 2048; t += 256) {                                  \
        int i_ = t >> 5, c4_ = t & 31;                                       \
        *(float4*)&Wst[i_ * WSS + c4_ * 4] =                                 \
            *(const float4*)&(WPTR)[i_ * 128 + c4_ * 4];                     \
    }                                                                        \
    __syncthreads();                                                         \
    _Pragma("unroll")                                                        \
    for (int kt = 0; kt < 8; ++kt) {                                         \
        const float* bp = Wst + (kt * 8 + ql) * WSS + n0 + qr;               \
        _Pragma("unroll")                                                    \
        for (int j = 0; j < 8; ++j) {                                        \
            uint32_t b0_ = f2tf(bp[j * 8]);                                  \
            uint32_t b1_ = f2tf(bp[4 * WSS + j * 8]);                        \
            mma_tf32(ACC[j][0], ACC[j][1], ACC[j][2], ACC[j][3],             \
                     af[kt][0], af[kt][1], af[kt][2], af[kt][3], b0_, b1_);  \
        }                                                                    \
    }                                                                        \
} while (0)

// ---------------- main fused kernel: one CTA per window ----------------
__global__ void __launch_bounds__(256, 1)
swin_block_kernel(const float* __restrict__ x,  const float* __restrict__ mask,
                  const float* __restrict__ qw, const float* __restrict__ qb,
                  const float* __restrict__ kw, const float* __restrict__ kb,
                  const float* __restrict__ vw, const float* __restrict__ vb,
                  const float* __restrict__ pw, const float* __restrict__ pb,
                  const float* __restrict__ ls, float* __restrict__ out)
{
    extern __shared__ float sm[];
    float* qs  = sm + OFF_Q;
    float* kss = sm + OFF_K;
    float* vsm = sm + OFF_V;
    float* Wst = sm + OFF_W;

    const int b    = blockIdx.x;
    const int tid  = threadIdx.x;
    const int warp = tid >> 5;
    const int lane = tid & 31;
    const int r0   = (warp & 3) * 16;       // output row tile
    const int n0   = (warp >> 2) * 64;      // output col tile
    const int qr   = lane >> 2;             // quad row 0..7
    const int ql   = lane & 3;              // quad col 0..3

    const float* xg = x + (size_t)b * (NTOK * CDIM);

    // load x [64][256] into qs (fp32, stride QS) — doubles as residual store
    for (int t = tid; t < 64 * 64; t += 256) {
        int i = t >> 6, c4 = t & 63;
        *(float4*)&qs[i * QS + c4 * 4] = ((const float4*)xg)[i * 64 + c4];
    }
    __syncthreads();

    // =========== Phase 1: QKV dual-branch residual linears via tf32 mma ===========
    for (int s = 0; s < 2; ++s) {
        float accQ[8][4], accK[8][4], accV[8][4];
#pragma unroll
        for (int j = 0; j < 8; ++j)
#pragma unroll
            for (int e = 0; e < 4; ++e) { accQ[j][e] = 0.f; accK[j][e] = 0.f; accV[j][e] = 0.f; }

        for (int half = 0; half < 2; ++half) {
            // A fragments for this K-half, shared across q,k,v (conflict-free loads)
            uint32_t af[8][4];
            const int cb = s * 128 + half * 64;
#pragma unroll
            for (int kt = 0; kt < 8; ++kt) {
                const float* ap = qs + (r0 + qr) * QS + cb + kt * 8 + ql;
                af[kt][0] = f2tf(ap[0]);
                af[kt][1] = f2tf(ap[8 * QS]);
                af[kt][2] = f2tf(ap[4]);
                af[kt][3] = f2tf(ap[8 * QS + 4]);
            }
            const int woff = s * 16384 + half * 8192;
            DO_GEMM(qw + woff, accQ);
            DO_GEMM(kw + woff, accK);
            DO_GEMM(vw + woff, accV);
        }

        // epilogues: k, v first (x still intact in qs), then sync, then q in place
        const float* xrow0 = qs + (r0 + qr) * QS + s * 128;
        const float* xrow1 = xrow0 + 8 * QS;
#pragma unroll
        for (int j = 0; j < 8; ++j) {
            int c = n0 + j * 8 + 2 * ql;
            float2 x0 = *(const float2*)&xrow0[c];
            float2 x1 = *(const float2*)&xrow1[c];
            float2 kb2 = *(const float2*)&kb[s * 128 + c];
            float2 vb2 = *(const float2*)&vb[s * 128 + c];
            *(float2*)&kss[(r0 + qr) * QS + s * 128 + c] =
                make_float2(x0.x + accK[j][0] + kb2.x, x0.y + accK[j][1] + kb2.y);
            *(float2*)&kss[(r0 + qr + 8) * QS + s * 128 + c] =
                make_float2(x1.x + accK[j][2] + kb2.x, x1.y + accK[j][3] + kb2.y);
            *(float2*)&vsm[(r0 + qr) * VSTR + s * 128 + c] =
                make_float2(x0.x + accV[j][0] + vb2.x, x0.y + accV[j][1] + vb2.y);
            *(float2*)&vsm[(r0 + qr + 8) * VSTR + s * 128 + c] =
                make_float2(x1.x + accV[j][2] + vb2.x, x1.y + accV[j][3] + vb2.y);
        }
        __syncthreads();   // all warps done reading x(branch s) before q overwrites it
#pragma unroll
        for (int j = 0; j < 8; ++j) {
            int c = n0 + j * 8 + 2 * ql;
            float2 x0 = *(const float2*)&xrow0[c];
            float2 x1 = *(const float2*)&xrow1[c];
            float2 qb2 = *(const float2*)&qb[s * 128 + c];
            *(float2*)&qs[(r0 + qr) * QS + s * 128 + c] =
                make_float2(x0.x + accQ[j][0] + qb2.x, x0.y + accQ[j][1] + qb2.y);
            *(float2*)&qs[(r0 + qr + 8) * QS + s * 128 + c] =
                make_float2(x1.x + accQ[j][2] + qb2.x, x1.y + accQ[j][3] + qb2.y);
        }
    }
    __syncthreads();

    // =========== Phase 2: l2-normalize q,k per (head,row); fold logit scale into q ===========
#pragma unroll
    for (int t4 = 0; t4 < 4; ++t4) {
        int t = tid + t4 * 256;
        int bufsel = t >> 9;
        int h = (t >> 6) & 7;
        int i = t & 63;
        float* base = (bufsel ? kss : qs) + i * QS + h * HD;
        float4 vv[8];
        float ssq = 0.f;
#pragma unroll
        for (int u = 0; u < 8; ++u) {
            vv[u] = ((float4*)base)[u];
            ssq = fmaf(vv[u].x, vv[u].x, ssq);
            ssq = fmaf(vv[u].y, vv[u].y, ssq);
            ssq = fmaf(vv[u].z, vv[u].z, ssq);
            ssq = fmaf(vv[u].w, vv[u].w, ssq);
        }
        float inv = 1.f / fmaxf(sqrtf(ssq), 1e-12f);
        if (bufsel == 0) inv *= fminf(expf(ls[h]), 100.f);
#pragma unroll
        for (int u = 0; u < 8; ++u) {
            vv[u].x *= inv; vv[u].y *= inv; vv[u].z *= inv; vv[u].w *= inv;
            ((float4*)base)[u] = vv[u];
        }
    }
    __syncthreads();

    // =========== Phase 3: attention, scalar fp32, per (head,row) in registers ===========
    const float* maskw = mask + (size_t)(b & (NWIN - 1)) * (NTOK * NTOK);
#pragma unroll 1
    for (int rr = 0; rr < 2; ++rr) {
        int row = tid + rr * 256;
        int h = row >> 6;
        int i = row & 63;

        const float4* qrow = (const float4*)(qs + i * QS + h * HD);
        float4 qv[8];
#pragma unroll
        for (int u = 0; u < 8; ++u) qv[u] = qrow[u];

        const float* bptr = d_biasS + h * 4096 + i * 64;
        const float* mptr = maskw + i * 64;

        float lg[64];
#pragma unroll
        for (int m = 0; m < 64; ++m) {
            const float4* krow = (const float4*)(kss + m * QS + h * HD);
            float dacc = 0.f;
#pragma unroll
            for (int u = 0; u < 8; ++u) {
                float4 kv = krow[u];
                dacc = fmaf(qv[u].x, kv.x, dacc);
                dacc = fmaf(qv[u].y, kv.y, dacc);
                dacc = fmaf(qv[u].z, kv.z, dacc);
                dacc = fmaf(qv[u].w, kv.w, dacc);
            }
            lg[m] = dacc + bptr[m] + mptr[m];
        }

        float mx = lg[0];
#pragma unroll
        for (int m = 1; m < 64; ++m) mx = fmaxf(mx, lg[m]);
        float ssum = 0.f;
#pragma unroll
        for (int m = 0; m < 64; ++m) { lg[m] = expf(lg[m] - mx); ssum += lg[m]; }
        float isum = 1.f / ssum;

        float4 oacc[8];
#pragma unroll
        for (int u = 0; u < 8; ++u) oacc[u] = make_float4(0.f, 0.f, 0.f, 0.f);
#pragma unroll
        for (int m = 0; m < 64; ++m) {
            const float4* vrow = (const float4*)(vsm + m * VSTR + h * HD);
            float wv = lg[m];
#pragma unroll
            for (int u = 0; u < 8; ++u) {
                float4 vvv = vrow[u];
                oacc[u].x = fmaf(wv, vvv.x, oacc[u].x);
                oacc[u].y = fmaf(wv, vvv.y, oacc[u].y);
                oacc[u].z = fmaf(wv, vvv.z, oacc[u].z);
                oacc[u].w = fmaf(wv, vvv.w, oacc[u].w);
            }
        }
        float4* orow = (float4*)(qs + i * QS + h * HD);
#pragma unroll
        for (int u = 0; u < 8; ++u) {
            oacc[u].x *= isum; oacc[u].y *= isum; oacc[u].z *= isum; oacc[u].w *= isum;
            orow[u] = oacc[u];
        }
    }
    __syncthreads();

    // =========== Phase 4: output projection via tf32 mma, store to gmem ===========
    float* og = out + (size_t)b * (NTOK * CDIM);
    for (int s = 0; s < 2; ++s) {
        float accP[8][4];
#pragma unroll
        for (int j = 0; j < 8; ++j)
#pragma unroll
            for (int e = 0; e < 4; ++e) accP[j][e] = 0.f;

        for (int half = 0; half < 2; ++half) {
            uint32_t af[8][4];
            const int cb = s * 128 + half * 64;
#pragma unroll
            for (int kt = 0; kt < 8; ++kt) {
                const float* ap = qs + (r0 + qr) * QS + cb + kt * 8 + ql;
                af[kt][0] = f2tf(ap[0]);
                af[kt][1] = f2tf(ap[8 * QS]);
                af[kt][2] = f2tf(ap[4]);
                af[kt][3] = f2tf(ap[8 * QS + 4]);
            }
            DO_GEMM(pw + s * 16384 + half * 8192, accP);
        }
#pragma unroll
        for (int j = 0; j < 8; ++j) {
            int c = n0 + j * 8 + 2 * ql;
            float2 pb2 = *(const float2*)&pb[s * 128 + c];
            *(float2*)&og[(r0 + qr) * CDIM + s * 128 + c] =
                make_float2(accP[j][0] + pb2.x, accP[j][1] + pb2.y);
            *(float2*)&og[(r0 + qr + 8) * CDIM + s * 128 + c] =
                make_float2(accP[j][2] + pb2.x, accP[j][3] + pb2.y);
        }
    }
}

extern "C" void kernel_launch(void* const* d_in, const int* in_sizes, int n_in,
                              void* d_out, int out_size) {
    const float* x    = (const float*)d_in[0];
    const float* mask = (const float*)d_in[1];
    const float* qw   = (const float*)d_in[2];
    const float* qb   = (const float*)d_in[3];
    const float* kw   = (const float*)d_in[4];
    const float* kb   = (const float*)d_in[5];
    const float* vw   = (const float*)d_in[6];
    const float* vb   = (const float*)d_in[7];
    const float* pw   = (const float*)d_in[8];
    const float* pb   = (const float*)d_in[9];
    const float* w1   = (const float*)d_in[10];
    const float* b1   = (const float*)d_in[11];
    const float* w2   = (const float*)d_in[12];
    const float* ls   = (const float*)d_in[13];
    const float* rpb  = (const float*)d_in[14];
    const int*   rpi  = (const int*)d_in[15];
    float* out = (float*)d_out;

    static bool inited = false;
    if (!inited) {
        cudaFuncSetAttribute(swin_block_kernel,
                             cudaFuncAttributeMaxDynamicSharedMemorySize, SMEM_BYTES);
        inited = true;
    }

    cpb_mlp_kernel<<<225, 128>>>(rpb, w1, b1, w2);
    bias_gather_kernel<<<(NHEADS * NTOK * NTOK + 255) / 256, 256>>>(rpi);
    swin_block_kernel<<<NBATCH, 256, SMEM_BYTES>>>(x, mask, qw, qb, kw, kb,
                                                   vw, vb, pw, pb, ls, out);
}

// round 4
// speedup vs baseline: 2.4070x; 1.8814x over previous
#include <cuda_runtime.h>
#include <math.h>
#include <stdint.h>

#define NTOK 64
#define CDIM 256
#define NHEADS 8
#define HD   32
#define QS   260          // row stride (floats) for q/k/v smem buffers
#define NWIN 64
#define NBATCH 2048

#define SMEM_FLOATS (3 * NTOK * QS)
#define SMEM_BYTES  (SMEM_FLOATS * 4)     // 199680 B

__device__ float d_tbl2[225 * NHEADS];
__device__ float d_Tcomb[NWIN * NHEADS * NTOK * NTOK];   // 16*sigmoid(bias)+mask, 8MB

// ---------------- prologue 1: rpb_table -> MLP -> (225, 8) ----------------
__global__ void cpb_mlp_kernel(const float* __restrict__ rpb,
                               const float* __restrict__ w1,
                               const float* __restrict__ b1,
                               const float* __restrict__ w2) {
    __shared__ float acc[NHEADS];
    int p = blockIdx.x;          // 0..224
    int j = threadIdx.x;         // 0..127
    if (j < NHEADS) acc[j] = 0.f;
    __syncthreads();
    float t0 = rpb[p * 2 + 0];
    float t1 = rpb[p * 2 + 1];
    float hid = fmaxf(t0 * w1[j] + t1 * w1[128 + j] + b1[j], 0.f);
#pragma unroll
    for (int h = 0; h < NHEADS; ++h) {
        float pv = hid * w2[j * 8 + h];
#pragma unroll
        for (int o = 16; o; o >>= 1) pv += __shfl_xor_sync(0xffffffffu, pv, o);
        if ((j & 31) == 0) atomicAdd(&acc[h], pv);
    }
    __syncthreads();
    if (j < NHEADS) d_tbl2[p * 8 + j] = acc[j];
}

// ---------------- prologue 2: combined bias+mask table ----------------
__global__ void bias_combine_kernel(const int* __restrict__ rpi,
                                    const float* __restrict__ mask) {
    int idx = blockIdx.x * blockDim.x + threadIdx.x;
    if (idx >= NWIN * NHEADS * NTOK * NTOK) return;
    int ij = idx & 4095;
    int h  = (idx >> 12) & 7;
    int w  = idx >> 15;
    float bv = d_tbl2[rpi[ij] * 8 + h];
    d_Tcomb[idx] = 16.f / (1.f + expf(-bv)) + mask[w * 4096 + ij];
}

// ---------------- mma helpers ----------------
__device__ __forceinline__ void mma_tf32(float& d0, float& d1, float& d2, float& d3,
                                         uint32_t a0, uint32_t a1, uint32_t a2, uint32_t a3,
                                         uint32_t b0, uint32_t b1) {
    asm volatile(
        "mma.sync.aligned.m16n8k8.row.col.f32.tf32.tf32.f32 "
        "{%0,%1,%2,%3},{%4,%5,%6,%7},{%8,%9},{%0,%1,%2,%3};"
        : "+f"(d0), "+f"(d1), "+f"(d2), "+f"(d3)
        : "r"(a0), "r"(a1), "r"(a2), "r"(a3), "r"(b0), "r"(b1));
}
__device__ __forceinline__ uint32_t f2tf(float f) {
    uint32_t u; asm("cvt.rna.tf32.f32 %0, %1;" : "=r"(u) : "f"(f)); return u;
}

// ---- full [64][128] weight stage: 8 float4 per thread ----
// rows: (tid>>5) + 8k, col: (tid&31)*4  -> coalesced LDG, conflict-free STS.128
#define LDW(P) do {                                                          \
    _Pragma("unroll")                                                        \
    for (int k_ = 0; k_ < 8; ++k_)                                           \
        wreg[k_] = *(const float4*)&(P)[(ldrow + 8 * k_) * 128 + ldcol];     \
} while (0)

#define STW() do {                                                           \
    _Pragma("unroll")                                                        \
    for (int k_ = 0; k_ < 8; ++k_) {                                         \
        uint4 u_;                                                            \
        u_.x = f2tf(wreg[k_].x); u_.y = f2tf(wreg[k_].y);                    \
        u_.z = f2tf(wreg[k_].z); u_.w = f2tf(wreg[k_].w);                    \
        *(uint4*)&stageW[(ldrow + 8 * k_) * QS + ldcol] = u_;                \
    }                                                                        \
} while (0)

#define MMA_LOOP(ACC) do {                                                   \
    _Pragma("unroll")                                                        \
    for (int kt = 0; kt < 8; ++kt) {                                         \
        const uint32_t* bp = stageU + (kt * 8 + ql) * QS + n0 + qr;          \
        _Pragma("unroll")                                                    \
        for (int j = 0; j < 8; ++j) {                                        \
            mma_tf32(ACC[j][0], ACC[j][1], ACC[j][2], ACC[j][3],             \
                     af[kt][0], af[kt][1], af[kt][2], af[kt][3],             \
                     bp[j * 8], bp[4 * QS + j * 8]);                         \
        }                                                                    \
    }                                                                        \
} while (0)

#define GEMM_STEP(NEXTP, ACC) do {                                           \
    __syncthreads();                                                         \
    STW();                                                                   \
    { const float* _np = (NEXTP); if (_np) LDW(_np); }                       \
    __syncthreads();                                                         \
    MMA_LOOP(ACC);                                                           \
} while (0)

// ---------------- main fused kernel: one CTA per window ----------------
__global__ void __launch_bounds__(256, 1)
swin_block_kernel(const float* __restrict__ x,
                  const float* __restrict__ qw, const float* __restrict__ qb,
                  const float* __restrict__ kw, const float* __restrict__ kb,
                  const float* __restrict__ vw, const float* __restrict__ vb,
                  const float* __restrict__ pw, const float* __restrict__ pb,
                  const float* __restrict__ ls, float* __restrict__ out)
{
    extern __shared__ float sm[];
    float* qs  = sm;
    float* kss = sm + NTOK * QS;
    float* vsm = sm + 2 * NTOK * QS;

    const int b    = blockIdx.x;
    const int tid  = threadIdx.x;
    const int warp = tid >> 5;
    const int lane = tid & 31;
    const int r0   = (warp & 3) * 16;       // GEMM output row tile
    const int n0   = (warp >> 2) * 64;      // GEMM output col tile
    const int qr   = lane >> 2;             // quad row 0..7
    const int ql   = lane & 3;              // quad col 0..3
    const int ldrow = tid >> 5;             // staging row base 0..7
    const int ldcol = (tid & 31) * 4;       // staging col 0..124

    const float* xg = x + (size_t)b * (NTOK * CDIM);
    const float* stageW; const uint32_t* stageU;
    float4 wreg[8];

    LDW(qw);                                 // preload first weight stage

    // load x [64][256] into qs (fp32, stride QS)
    for (int t = tid; t < 64 * 64; t += 256) {
        int i = t >> 6, c4 = t & 63;
        *(float4*)&qs[i * QS + c4 * 4] = ((const float4*)xg)[i * 64 + c4];
    }
    __syncthreads();

    // =========== Phase 1: QKV dual-branch residual linears (tf32 mma) ===========
    for (int s = 0; s < 2; ++s) {
        stageW = vsm + s * 128; stageU = (const uint32_t*)stageW;
        float accQ[8][4], accK[8][4], accV[8][4];
#pragma unroll
        for (int j = 0; j < 8; ++j)
#pragma unroll
            for (int e = 0; e < 4; ++e) { accQ[j][e] = 0.f; accK[j][e] = 0.f; accV[j][e] = 0.f; }

        for (int hf = 0; hf < 2; ++hf) {
            uint32_t af[8][4];
            const int cb = s * 128 + hf * 64;
#pragma unroll
            for (int kt = 0; kt < 8; ++kt) {
                const float* ap = qs + (r0 + qr) * QS + cb + kt * 8 + ql;
                af[kt][0] = f2tf(ap[0]);
                af[kt][1] = f2tf(ap[8 * QS]);
                af[kt][2] = f2tf(ap[4]);
                af[kt][3] = f2tf(ap[8 * QS + 4]);
            }
            const int wo = s * 16384 + hf * 8192;
            GEMM_STEP(kw + wo, accQ);
            GEMM_STEP(vw + wo, accK);
            const float* nxt = (hf == 0) ? (qw + wo + 8192)
                             : (s == 0)  ? (qw + 16384) : pw;
            GEMM_STEP(nxt, accV);
        }
        __syncthreads();   // all mma reads of staged weights done before v-write

        // epilogue: k, v, then q (q-write cells are read only by this thread)
        const float* xrow0 = qs + (r0 + qr) * QS + s * 128;
        const float* xrow1 = xrow0 + 8 * QS;
#pragma unroll
        for (int j = 0; j < 8; ++j) {
            int c = n0 + j * 8 + 2 * ql;
            float2 x0 = *(const float2*)&xrow0[c];
            float2 x1 = *(const float2*)&xrow1[c];
            float2 kb2 = *(const float2*)&kb[s * 128 + c];
            float2 vb2 = *(const float2*)&vb[s * 128 + c];
            *(float2*)&kss[(r0 + qr) * QS + s * 128 + c] =
                make_float2(x0.x + accK[j][0] + kb2.x, x0.y + accK[j][1] + kb2.y);
            *(float2*)&kss[(r0 + qr + 8) * QS + s * 128 + c] =
                make_float2(x1.x + accK[j][2] + kb2.x, x1.y + accK[j][3] + kb2.y);
            *(float2*)&vsm[(r0 + qr) * QS + s * 128 + c] =
                make_float2(x0.x + accV[j][0] + vb2.x, x0.y + accV[j][1] + vb2.y);
            *(float2*)&vsm[(r0 + qr + 8) * QS + s * 128 + c] =
                make_float2(x1.x + accV[j][2] + vb2.x, x1.y + accV[j][3] + vb2.y);
        }
#pragma unroll
        for (int j = 0; j < 8; ++j) {
            int c = n0 + j * 8 + 2 * ql;
            float2 x0 = *(const float2*)&xrow0[c];
            float2 x1 = *(const float2*)&xrow1[c];
            float2 qb2 = *(const float2*)&qb[s * 128 + c];
            *(float2*)&qs[(r0 + qr) * QS + s * 128 + c] =
                make_float2(x0.x + accQ[j][0] + qb2.x, x0.y + accQ[j][1] + qb2.y);
            *(float2*)&qs[(r0 + qr + 8) * QS + s * 128 + c] =
                make_float2(x1.x + accQ[j][2] + qb2.x, x1.y + accQ[j][3] + qb2.y);
        }
        __syncthreads();
    }

    // =========== Phase 2: l2-normalize q,k; fold logit scale into q ===========
#pragma unroll
    for (int t4 = 0; t4 < 4; ++t4) {
        int t = tid + t4 * 256;
        int bufsel = t >> 9;
        int h = (t >> 6) & 7;
        int i = t & 63;
        float* base = (bufsel ? kss : qs) + i * QS + h * HD;
        float4 vv[8];
        float ssq = 0.f;
#pragma unroll
        for (int u = 0; u < 8; ++u) {
            vv[u] = ((float4*)base)[u];
            ssq = fmaf(vv[u].x, vv[u].x, ssq);
            ssq = fmaf(vv[u].y, vv[u].y, ssq);
            ssq = fmaf(vv[u].z, vv[u].z, ssq);
            ssq = fmaf(vv[u].w, vv[u].w, ssq);
        }
        float inv = 1.f / fmaxf(sqrtf(ssq), 1e-12f);
        if (bufsel == 0) inv *= fminf(expf(ls[h]), 100.f);
#pragma unroll
        for (int u = 0; u < 8; ++u) {
            vv[u].x *= inv; vv[u].y *= inv; vv[u].z *= inv; vv[u].w *= inv;
            ((float4*)base)[u] = vv[u];
        }
    }
    __syncthreads();

    // =========== Phase 3: attention via tf32 mma, one warp per head ===========
    {
        const int h = warp;
        const float* Tw = d_Tcomb + (size_t)(((b & (NWIN - 1)) * NHEADS + h) << 12);
        const int s0l = (lane & ~3) | (ql >> 1);
        const bool odd = ql & 1;

#pragma unroll 1
        for (int mt = 0; mt < 4; ++mt) {
            const int i0r = mt * 16 + qr;

            // Q A-frags (4 k-tiles over d=32)
            uint32_t qa[4][4];
#pragma unroll
            for (int kt = 0; kt < 4; ++kt) {
                const float* ap = qs + i0r * QS + h * HD + kt * 8 + ql;
                qa[kt][0] = f2tf(ap[0]);
                qa[kt][1] = f2tf(ap[8 * QS]);
                qa[kt][2] = f2tf(ap[4]);
                qa[kt][3] = f2tf(ap[8 * QS + 4]);
            }

            // S = Q K^T : 8 n-tiles over keys
            float S[8][4];
#pragma unroll
            for (int nt = 0; nt < 8; ++nt) { S[nt][0] = S[nt][1] = S[nt][2] = S[nt][3] = 0.f; }
#pragma unroll
            for (int kt = 0; kt < 4; ++kt) {
#pragma unroll
                for (int nt = 0; nt < 8; ++nt) {
                    const float* kp = kss + (nt * 8 + qr) * QS + h * HD + kt * 8 + ql;
                    uint32_t b0 = f2tf(kp[0]);
                    uint32_t b1 = f2tf(kp[4]);
                    mma_tf32(S[nt][0], S[nt][1], S[nt][2], S[nt][3],
                             qa[kt][0], qa[kt][1], qa[kt][2], qa[kt][3], b0, b1);
                }
            }

            // + combined bias+mask, row max
            float rmax0 = -1e30f, rmax1 = -1e30f;
#pragma unroll
            for (int nt = 0; nt < 8; ++nt) {
                float2 t0 = *(const float2*)&Tw[i0r * 64 + nt * 8 + 2 * ql];
                float2 t1 = *(const float2*)&Tw[(i0r + 8) * 64 + nt * 8 + 2 * ql];
                S[nt][0] += t0.x; S[nt][1] += t0.y;
                S[nt][2] += t1.x; S[nt][3] += t1.y;
                rmax0 = fmaxf(rmax0, fmaxf(S[nt][0], S[nt][1]));
                rmax1 = fmaxf(rmax1, fmaxf(S[nt][2], S[nt][3]));
            }
            rmax0 = fmaxf(rmax0, __shfl_xor_sync(0xffffffffu, rmax0, 1));
            rmax0 = fmaxf(rmax0, __shfl_xor_sync(0xffffffffu, rmax0, 2));
            rmax1 = fmaxf(rmax1, __shfl_xor_sync(0xffffffffu, rmax1, 1));
            rmax1 = fmaxf(rmax1, __shfl_xor_sync(0xffffffffu, rmax1, 2));

            float sum0 = 0.f, sum1 = 0.f;
#pragma unroll
            for (int nt = 0; nt < 8; ++nt) {
                S[nt][0] = __expf(S[nt][0] - rmax0); sum0 += S[nt][0];
                S[nt][1] = __expf(S[nt][1] - rmax0); sum0 += S[nt][1];
                S[nt][2] = __expf(S[nt][2] - rmax1); sum1 += S[nt][2];
                S[nt][3] = __expf(S[nt][3] - rmax1); sum1 += S[nt][3];
            }
            sum0 += __shfl_xor_sync(0xffffffffu, sum0, 1);
            sum0 += __shfl_xor_sync(0xffffffffu, sum0, 2);
            sum1 += __shfl_xor_sync(0xffffffffu, sum1, 1);
            sum1 += __shfl_xor_sync(0xffffffffu, sum1, 2);
            float inv0 = 1.f / sum0, inv1 = 1.f / sum1;

            // re-layout P (C-layout) -> A-frags via quad shuffles
            uint32_t pa[8][4];
#pragma unroll
            for (int nt = 0; nt < 8; ++nt) {
                uint32_t u0 = f2tf(S[nt][0]), u1 = f2tf(S[nt][1]);
                uint32_t u2 = f2tf(S[nt][2]), u3 = f2tf(S[nt][3]);
                uint32_t v0 = __shfl_sync(0xffffffffu, u0, s0l);
                uint32_t v1 = __shfl_sync(0xffffffffu, u1, s0l);
                pa[nt][0] = odd ? v1 : v0;
                uint32_t v2 = __shfl_sync(0xffffffffu, u2, s0l);
                uint32_t v3 = __shfl_sync(0xffffffffu, u3, s0l);
                pa[nt][1] = odd ? v3 : v2;
                v0 = __shfl_sync(0xffffffffu, u0, s0l + 2);
                v1 = __shfl_sync(0xffffffffu, u1, s0l + 2);
                pa[nt][2] = odd ? v1 : v0;
                v2 = __shfl_sync(0xffffffffu, u2, s0l + 2);
                v3 = __shfl_sync(0xffffffffu, u3, s0l + 2);
                pa[nt][3] = odd ? v3 : v2;
            }

            // O = P V : 4 n-tiles over d=32, accumulate over 8 key k-tiles
            float O[4][4];
#pragma unroll
            for (int nd = 0; nd < 4; ++nd) { O[nd][0] = O[nd][1] = O[nd][2] = O[nd][3] = 0.f; }
#pragma unroll
            for (int kt = 0; kt < 8; ++kt) {
#pragma unroll
                for (int nd = 0; nd < 4; ++nd) {
                    const float* vp = vsm + (kt * 8 + ql) * QS + h * HD + nd * 8 + qr;
                    uint32_t b0 = f2tf(vp[0]);
                    uint32_t b1 = f2tf(vp[4 * QS]);
                    mma_tf32(O[nd][0], O[nd][1], O[nd][2], O[nd][3],
                             pa[kt][0], pa[kt][1], pa[kt][2], pa[kt][3], b0, b1);
                }
            }

            // epilogue: normalize, cvt to tf32 bits, overwrite q rows (own head cols)
#pragma unroll
            for (int nd = 0; nd < 4; ++nd) {
                uint2 st0, st1;
                st0.x = f2tf(O[nd][0] * inv0); st0.y = f2tf(O[nd][1] * inv0);
                st1.x = f2tf(O[nd][2] * inv1); st1.y = f2tf(O[nd][3] * inv1);
                *(uint2*)&qs[i0r * QS + h * HD + nd * 8 + 2 * ql] = st0;
                *(uint2*)&qs[(i0r + 8) * QS + h * HD + nd * 8 + 2 * ql] = st1;
            }
        }
    }
    __syncthreads();   // all O (tf32 bits) written before phase-4 A-frag reads

    // =========== Phase 4: output projection (tf32 mma), store to gmem ===========
    float* og = out + (size_t)b * (NTOK * CDIM);
    for (int s = 0; s < 2; ++s) {
        stageW = vsm + s * 128; stageU = (const uint32_t*)stageW;
        float accP[8][4];
#pragma unroll
        for (int j = 0; j < 8; ++j)
#pragma unroll
            for (int e = 0; e < 4; ++e) accP[j][e] = 0.f;

        for (int hf = 0; hf < 2; ++hf) {
            uint32_t af[8][4];
            const int cb = s * 128 + hf * 64;
#pragma unroll
            for (int kt = 0; kt < 8; ++kt) {
                const uint32_t* ap = (const uint32_t*)qs + (r0 + qr) * QS + cb + kt * 8 + ql;
                af[kt][0] = ap[0];
                af[kt][1] = ap[8 * QS];
                af[kt][2] = ap[4];
                af[kt][3] = ap[8 * QS + 4];
            }
            const float* nxt = (s == 0) ? (pw + (hf == 0 ? 8192 : 16384))
                             : (hf == 0) ? (pw + 24576) : (const float*)0;
            GEMM_STEP(nxt, accP);
        }
#pragma unroll
        for (int j = 0; j < 8; ++j) {
            int c = n0 + j * 8 + 2 * ql;
            float2 pb2 = *(const float2*)&pb[s * 128 + c];
            *(float2*)&og[(r0 + qr) * CDIM + s * 128 + c] =
                make_float2(accP[j][0] + pb2.x, accP[j][1] + pb2.y);
            *(float2*)&og[(r0 + qr + 8) * CDIM + s * 128 + c] =
                make_float2(accP[j][2] + pb2.x, accP[j][3] + pb2.y);
        }
    }
}

extern "C" void kernel_launch(void* const* d_in, const int* in_sizes, int n_in,
                              void* d_out, int out_size) {
    const float* x    = (const float*)d_in[0];
    const float* mask = (const float*)d_in[1];
    const float* qw   = (const float*)d_in[2];
    const float* qb   = (const float*)d_in[3];
    const float* kw   = (const float*)d_in[4];
    const float* kb   = (const float*)d_in[5];
    const float* vw   = (const float*)d_in[6];
    const float* vb   = (const float*)d_in[7];
    const float* pw   = (const float*)d_in[8];
    const float* pb   = (const float*)d_in[9];
    const float* w1   = (const float*)d_in[10];
    const float* b1   = (const float*)d_in[11];
    const float* w2   = (const float*)d_in[12];
    const float* ls   = (const float*)d_in[13];
    const float* rpb  = (const float*)d_in[14];
    const int*   rpi  = (const int*)d_in[15];
    float* out = (float*)d_out;

    static bool inited = false;
    if (!inited) {
        cudaFuncSetAttribute(swin_block_kernel,
                             cudaFuncAttributeMaxDynamicSharedMemorySize, SMEM_BYTES);
        inited = true;
    }

    cpb_mlp_kernel<<<225, 128>>>(rpb, w1, b1, w2);
    bias_combine_kernel<<<(NWIN * NHEADS * NTOK * NTOK + 255) / 256, 256>>>(rpi, mask);
    swin_block_kernel<<<NBATCH, 256, SMEM_BYTES>>>(x, qw, qb, kw, kb,
                                                   vw, vb, pw, pb, ls, out);
}

// round 6
// speedup vs baseline: 2.9130x; 1.2102x over previous
#include <cuda_runtime.h>
#include <math.h>
#include <stdint.h>

#define NTOK 64
#define CDIM 256
#define NHEADS 8
#define HD   32
#define QS   260          // row stride (floats) for q/k/v smem buffers
#define NWIN 64
#define NBATCH 2048

#define SMEM_FLOATS (3 * NTOK * QS)
#define SMEM_BYTES  (SMEM_FLOATS * 4)     // 199680 B

__device__ float d_tbl2[225 * NHEADS];
__device__ float d_Tcomb[NWIN * NHEADS * NTOK * NTOK];   // 16*sigmoid(bias)+mask, 8MB
__device__ uint32_t d_wtf[4 * 32768];                    // q,k,v,p weights as tf32 bits

// ---------------- prologue 0: weights -> tf32 bits ----------------
__device__ __forceinline__ uint32_t f2tf(float f) {
    uint32_t u; asm("cvt.rna.tf32.f32 %0, %1;" : "=r"(u) : "f"(f)); return u;
}

__global__ void wconv_kernel(const float* __restrict__ qw, const float* __restrict__ kw,
                             const float* __restrict__ vw, const float* __restrict__ pw) {
    int idx = blockIdx.x * blockDim.x + threadIdx.x;
    if (idx >= 4 * 32768) return;
    int sel = idx >> 15, off = idx & 32767;
    float v = (sel == 0) ? qw[off] : (sel == 1) ? kw[off] : (sel == 2) ? vw[off] : pw[off];
    d_wtf[idx] = f2tf(v);
}

// ---------------- prologue 1: rpb_table -> MLP -> (225, 8) ----------------
__global__ void cpb_mlp_kernel(const float* __restrict__ rpb,
                               const float* __restrict__ w1,
                               const float* __restrict__ b1,
                               const float* __restrict__ w2) {
    __shared__ float acc[NHEADS];
    int p = blockIdx.x;          // 0..224
    int j = threadIdx.x;         // 0..127
    if (j < NHEADS) acc[j] = 0.f;
    __syncthreads();
    float t0 = rpb[p * 2 + 0];
    float t1 = rpb[p * 2 + 1];
    float hid = fmaxf(t0 * w1[j] + t1 * w1[128 + j] + b1[j], 0.f);
#pragma unroll
    for (int h = 0; h < NHEADS; ++h) {
        float pv = hid * w2[j * 8 + h];
#pragma unroll
        for (int o = 16; o; o >>= 1) pv += __shfl_xor_sync(0xffffffffu, pv, o);
        if ((j & 31) == 0) atomicAdd(&acc[h], pv);
    }
    __syncthreads();
    if (j < NHEADS) d_tbl2[p * 8 + j] = acc[j];
}

// ---------------- prologue 2: combined bias+mask table ----------------
__global__ void bias_combine_kernel(const int* __restrict__ rpi,
                                    const float* __restrict__ mask) {
    int idx = blockIdx.x * blockDim.x + threadIdx.x;
    if (idx >= NWIN * NHEADS * NTOK * NTOK) return;
    int ij = idx & 4095;
    int h  = (idx >> 12) & 7;
    int w  = idx >> 15;
    float bv = d_tbl2[rpi[ij] * 8 + h];
    d_Tcomb[idx] = 16.f / (1.f + expf(-bv)) + mask[w * 4096 + ij];
}

// ---------------- mma helper ----------------
__device__ __forceinline__ void mma_tf32(float& d0, float& d1, float& d2, float& d3,
                                         uint32_t a0, uint32_t a1, uint32_t a2, uint32_t a3,
                                         uint32_t b0, uint32_t b1) {
    asm volatile(
        "mma.sync.aligned.m16n8k8.row.col.f32.tf32.tf32.f32 "
        "{%0,%1,%2,%3},{%4,%5,%6,%7},{%8,%9},{%0,%1,%2,%3};"
        : "+f"(d0), "+f"(d1), "+f"(d2), "+f"(d3)
        : "r"(a0), "r"(a1), "r"(a2), "r"(a3), "r"(b0), "r"(b1));
}

// weight source in d_wtf: w 0..3 = q,k,v,p
#define WSRC(w, s, hf) (d_wtf + (w) * 32768 + (s) * 16384 + (hf) * 8192)

// stage buffer for stage index T (compile-time literal after unrolling):
// even -> vsm strip, odd -> kss strip; col region 128 for stages 6..11
#define BUF_PTR(T) ((const uint32_t*)((((T) & 1) ? (void*)kss : (void*)vsm)) + \
                    ((((T) >= 6) && ((T) < 12)) ? 128 : 0))
#define BUF_ADR(T) (((((T) & 1) ? kss_u : vsm_u)) + ((((T) >= 6) && ((T) < 12)) ? 512u : 0u))

// issue the 8 cp.async for one [64][128] weight stage + commit
#define ISSUE(SRC, DSTU) do {                                                \
    const uint32_t* _s0 = (SRC) + ldrow * 128 + ldcol;                       \
    uint32_t _d0 = (DSTU) + (uint32_t)((ldrow * QS + ldcol) * 4);            \
    _Pragma("unroll")                                                        \
    for (int k_ = 0; k_ < 8; ++k_)                                           \
        asm volatile("cp.async.cg.shared.global [%0], [%1], 16;\n"           \
            :: "r"(_d0 + (uint32_t)(k_ * 8 * QS * 4)),                       \
               "l"(_s0 + k_ * 8 * 128) : "memory");                          \
    asm volatile("cp.async.commit_group;\n" ::: "memory");                   \
} while (0)

// 32x32 warp-tile mma over one staged [64 K][128 N] weight tile
#define MMA_LOOP32(BUFP, ACC) do {                                           \
    const uint32_t* _bu = (BUFP);                                            \
    _Pragma("unroll")                                                        \
    for (int kt = 0; kt < 8; ++kt) {                                         \
        const uint32_t* bp = _bu + (kt * 8 + ql) * QS + n0 + qr;             \
        _Pragma("unroll")                                                    \
        for (int nt = 0; nt < 4; ++nt) {                                     \
            uint32_t b0_ = bp[nt * 8], b1_ = bp[4 * QS + nt * 8];            \
            mma_tf32(ACC[0][nt][0], ACC[0][nt][1], ACC[0][nt][2], ACC[0][nt][3], \
                     af[0][kt][0], af[0][kt][1], af[0][kt][2], af[0][kt][3], b0_, b1_); \
            mma_tf32(ACC[1][nt][0], ACC[1][nt][1], ACC[1][nt][2], ACC[1][nt][3], \
                     af[1][kt][0], af[1][kt][1], af[1][kt][2], af[1][kt][3], b0_, b1_); \
        }                                                                    \
    }                                                                        \
} while (0)

// pipelined stage: wait prefetched group, sync, prefetch next, mma current
#define STAGE(NEXTSRC, NEXTDSTU, CURBUF, ACC) do {                           \
    asm volatile("cp.async.wait_group 0;\n" ::: "memory");                   \
    __syncthreads();                                                         \
    { const uint32_t* _ns = (NEXTSRC); if (_ns) ISSUE(_ns, NEXTDSTU); }      \
    MMA_LOOP32(CURBUF, ACC);                                                 \
} while (0)

#define LOAD_AF_F32(CB) do {                                                 \
    _Pragma("unroll")                                                        \
    for (int mt = 0; mt < 2; ++mt)                                           \
    _Pragma("unroll")                                                        \
    for (int kt = 0; kt < 8; ++kt) {                                         \
        const float* ap = qs + (r0m + mt * 16 + qr) * QS + (CB) + kt * 8 + ql; \
        af[mt][kt][0] = f2tf(ap[0]);                                         \
        af[mt][kt][1] = f2tf(ap[8 * QS]);                                    \
        af[mt][kt][2] = f2tf(ap[4]);                                         \
        af[mt][kt][3] = f2tf(ap[8 * QS + 4]);                                \
    }                                                                        \
} while (0)

#define LOAD_AF_BITS(CB) do {                                                \
    _Pragma("unroll")                                                        \
    for (int mt = 0; mt < 2; ++mt)                                           \
    _Pragma("unroll")                                                        \
    for (int kt = 0; kt < 8; ++kt) {                                         \
        const uint32_t* ap = qsu + (r0m + mt * 16 + qr) * QS + (CB) + kt * 8 + ql; \
        af[mt][kt][0] = ap[0];                                               \
        af[mt][kt][1] = ap[8 * QS];                                          \
        af[mt][kt][2] = ap[4];                                               \
        af[mt][kt][3] = ap[8 * QS + 4];                                      \
    }                                                                        \
} while (0)

// ---------------- main fused kernel: one CTA per window ----------------
__global__ void __launch_bounds__(256, 1)
swin_block_kernel(const float* __restrict__ x,
                  const float* __restrict__ qb, const float* __restrict__ kb,
                  const float* __restrict__ vb, const float* __restrict__ pb,
                  const float* __restrict__ ls, float* __restrict__ out)
{
    extern __shared__ float sm[];
    float* qs  = sm;
    float* kss = sm + NTOK * QS;
    float* vsm = sm + 2 * NTOK * QS;
    const uint32_t* qsu = (const uint32_t*)qs;

    const int b    = blockIdx.x;
    const int tid  = threadIdx.x;
    const int warp = tid >> 5;
    const int lane = tid & 31;
    const int r0m  = (warp & 1) * 32;       // warp row-tile base (2 mtiles of 16)
    const int n0   = (warp >> 1) * 32;      // warp col-tile base (4 ntiles of 8)
    const int qr   = lane >> 2;             // quad row 0..7
    const int ql   = lane & 3;              // quad col 0..3
    const int ldrow = tid >> 5;             // staging row base 0..7
    const int ldcol = (tid & 31) * 4;       // staging col 0..124

    const uint32_t vsm_u = (uint32_t)__cvta_generic_to_shared(vsm);
    const uint32_t kss_u = (uint32_t)__cvta_generic_to_shared(kss);

    uint32_t af[2][8][4];

    // prefetch stage 0 (qw s0 hf0) into vsm strip
    ISSUE(WSRC(0, 0, 0), BUF_ADR(0));

    // load x [64][256] into qs (fp32, stride QS)
    const float* xg = x + (size_t)b * (NTOK * CDIM);
    for (int t = tid; t < 64 * 64; t += 256) {
        int i = t >> 6, c4 = t & 63;
        *(float4*)&qs[i * QS + c4 * 4] = ((const float4*)xg)[i * 64 + c4];
    }
    __syncthreads();   // x visible to ALL warps before any A-fragment load (R5 bug fix)

    // =========== Phase 1: QKV dual-branch residual linears ===========
#pragma unroll
    for (int s = 0; s < 2; ++s) {
        float accQ[2][4][4], accK[2][4][4], accV[2][4][4];
#pragma unroll
        for (int mt = 0; mt < 2; ++mt)
#pragma unroll
            for (int nt = 0; nt < 4; ++nt)
#pragma unroll
                for (int e = 0; e < 4; ++e) {
                    accQ[mt][nt][e] = 0.f; accK[mt][nt][e] = 0.f; accV[mt][nt][e] = 0.f;
                }

#pragma unroll
        for (int hf = 0; hf < 2; ++hf) {
            LOAD_AF_F32(s * 128 + hf * 64);
            const int t0 = (s * 2 + hf) * 3;
            STAGE(WSRC(1, s, hf), BUF_ADR(t0 + 1), BUF_PTR(t0 + 0), accQ);
            STAGE(WSRC(2, s, hf), BUF_ADR(t0 + 2), BUF_PTR(t0 + 1), accK);
            const uint32_t* nxt = (hf == 0) ? WSRC(0, s, 1)
                                : (s == 0)  ? WSRC(0, 1, 0) : (const uint32_t*)0;
            STAGE(nxt, BUF_ADR(t0 + 3 < 12 ? t0 + 3 : 0), BUF_PTR(t0 + 2), accV);
        }
        __syncthreads();   // all mma reads of staged weights done before epilogue writes

        // epilogue: residual + bias -> k,v then q (each thread owns its x cells)
#pragma unroll
        for (int mt = 0; mt < 2; ++mt) {
            const int rr = r0m + mt * 16 + qr;
            const float* x0p = qs + rr * QS + s * 128;
            const float* x1p = x0p + 8 * QS;
#pragma unroll
            for (int nt = 0; nt < 4; ++nt) {
                const int c = n0 + nt * 8 + 2 * ql;
                float2 x0 = *(const float2*)&x0p[c];
                float2 x1 = *(const float2*)&x1p[c];
                float2 kb2 = *(const float2*)&kb[s * 128 + c];
                float2 vb2 = *(const float2*)&vb[s * 128 + c];
                float2 qb2 = *(const float2*)&qb[s * 128 + c];
                *(float2*)&kss[rr * QS + s * 128 + c] =
                    make_float2(x0.x + accK[mt][nt][0] + kb2.x, x0.y + accK[mt][nt][1] + kb2.y);
                *(float2*)&kss[(rr + 8) * QS + s * 128 + c] =
                    make_float2(x1.x + accK[mt][nt][2] + kb2.x, x1.y + accK[mt][nt][3] + kb2.y);
                *(float2*)&vsm[rr * QS + s * 128 + c] =
                    make_float2(x0.x + accV[mt][nt][0] + vb2.x, x0.y + accV[mt][nt][1] + vb2.y);
                *(float2*)&vsm[(rr + 8) * QS + s * 128 + c] =
                    make_float2(x1.x + accV[mt][nt][2] + vb2.x, x1.y + accV[mt][nt][3] + vb2.y);
                *(float2*)&qs[rr * QS + s * 128 + c] =
                    make_float2(x0.x + accQ[mt][nt][0] + qb2.x, x0.y + accQ[mt][nt][1] + qb2.y);
                *(float2*)&qs[(rr + 8) * QS + s * 128 + c] =
                    make_float2(x1.x + accQ[mt][nt][2] + qb2.x, x1.y + accQ[mt][nt][3] + qb2.y);
            }
        }
        __syncthreads();
    }

    // =========== Phase 2: l2-normalize q,k; fold logit scale into q ===========
#pragma unroll
    for (int t4 = 0; t4 < 4; ++t4) {
        int t = tid + t4 * 256;
        int bufsel = t >> 9;
        int h = (t >> 6) & 7;
        int i = t & 63;
        float* base = (bufsel ? kss : qs) + i * QS + h * HD;
        float4 vv[8];
        float ssq = 0.f;
#pragma unroll
        for (int u = 0; u < 8; ++u) {
            vv[u] = ((float4*)base)[u];
            ssq = fmaf(vv[u].x, vv[u].x, ssq);
            ssq = fmaf(vv[u].y, vv[u].y, ssq);
            ssq = fmaf(vv[u].z, vv[u].z, ssq);
            ssq = fmaf(vv[u].w, vv[u].w, ssq);
        }
        float inv = 1.f / fmaxf(sqrtf(ssq), 1e-12f);
        if (bufsel == 0) inv *= fminf(expf(ls[h]), 100.f);
#pragma unroll
        for (int u = 0; u < 8; ++u) {
            vv[u].x *= inv; vv[u].y *= inv; vv[u].z *= inv; vv[u].w *= inv;
            ((float4*)base)[u] = vv[u];
        }
    }
    __syncthreads();

    // =========== Phase 3: attention via tf32 mma, one warp per head ===========
    {
        const int h = warp;
        const float* Tw = d_Tcomb + (size_t)(((b & (NWIN - 1)) * NHEADS + h) << 12);
        const int s0l = (lane & ~3) | (ql >> 1);
        const bool odd = ql & 1;

#pragma unroll 1
        for (int mt = 0; mt < 4; ++mt) {
            const int i0r = mt * 16 + qr;

            uint32_t qa[4][4];
#pragma unroll
            for (int kt = 0; kt < 4; ++kt) {
                const float* ap = qs + i0r * QS + h * HD + kt * 8 + ql;
                qa[kt][0] = f2tf(ap[0]);
                qa[kt][1] = f2tf(ap[8 * QS]);
                qa[kt][2] = f2tf(ap[4]);
                qa[kt][3] = f2tf(ap[8 * QS + 4]);
            }

            float S[8][4];
#pragma unroll
            for (int nt = 0; nt < 8; ++nt) { S[nt][0] = S[nt][1] = S[nt][2] = S[nt][3] = 0.f; }
#pragma unroll
            for (int kt = 0; kt < 4; ++kt) {
#pragma unroll
                for (int nt = 0; nt < 8; ++nt) {
                    const float* kp = kss + (nt * 8 + qr) * QS + h * HD + kt * 8 + ql;
                    uint32_t b0 = f2tf(kp[0]);
                    uint32_t b1 = f2tf(kp[4]);
                    mma_tf32(S[nt][0], S[nt][1], S[nt][2], S[nt][3],
                             qa[kt][0], qa[kt][1], qa[kt][2], qa[kt][3], b0, b1);
                }
            }

            float rmax0 = -1e30f, rmax1 = -1e30f;
#pragma unroll
            for (int nt = 0; nt < 8; ++nt) {
                float2 t0 = *(const float2*)&Tw[i0r * 64 + nt * 8 + 2 * ql];
                float2 t1 = *(const float2*)&Tw[(i0r + 8) * 64 + nt * 8 + 2 * ql];
                S[nt][0] += t0.x; S[nt][1] += t0.y;
                S[nt][2] += t1.x; S[nt][3] += t1.y;
                rmax0 = fmaxf(rmax0, fmaxf(S[nt][0], S[nt][1]));
                rmax1 = fmaxf(rmax1, fmaxf(S[nt][2], S[nt][3]));
            }
            rmax0 = fmaxf(rmax0, __shfl_xor_sync(0xffffffffu, rmax0, 1));
            rmax0 = fmaxf(rmax0, __shfl_xor_sync(0xffffffffu, rmax0, 2));
            rmax1 = fmaxf(rmax1, __shfl_xor_sync(0xffffffffu, rmax1, 1));
            rmax1 = fmaxf(rmax1, __shfl_xor_sync(0xffffffffu, rmax1, 2));

            float sum0 = 0.f, sum1 = 0.f;
#pragma unroll
            for (int nt = 0; nt < 8; ++nt) {
                S[nt][0] = __expf(S[nt][0] - rmax0); sum0 += S[nt][0];
                S[nt][1] = __expf(S[nt][1] - rmax0); sum0 += S[nt][1];
                S[nt][2] = __expf(S[nt][2] - rmax1); sum1 += S[nt][2];
                S[nt][3] = __expf(S[nt][3] - rmax1); sum1 += S[nt][3];
            }
            sum0 += __shfl_xor_sync(0xffffffffu, sum0, 1);
            sum0 += __shfl_xor_sync(0xffffffffu, sum0, 2);
            sum1 += __shfl_xor_sync(0xffffffffu, sum1, 1);
            sum1 += __shfl_xor_sync(0xffffffffu, sum1, 2);
            float inv0 = 1.f / sum0, inv1 = 1.f / sum1;

            uint32_t pa[8][4];
#pragma unroll
            for (int nt = 0; nt < 8; ++nt) {
                uint32_t u0 = f2tf(S[nt][0]), u1 = f2tf(S[nt][1]);
                uint32_t u2 = f2tf(S[nt][2]), u3 = f2tf(S[nt][3]);
                uint32_t v0 = __shfl_sync(0xffffffffu, u0, s0l);
                uint32_t v1 = __shfl_sync(0xffffffffu, u1, s0l);
                pa[nt][0] = odd ? v1 : v0;
                uint32_t v2 = __shfl_sync(0xffffffffu, u2, s0l);
                uint32_t v3 = __shfl_sync(0xffffffffu, u3, s0l);
                pa[nt][1] = odd ? v3 : v2;
                v0 = __shfl_sync(0xffffffffu, u0, s0l + 2);
                v1 = __shfl_sync(0xffffffffu, u1, s0l + 2);
                pa[nt][2] = odd ? v1 : v0;
                v2 = __shfl_sync(0xffffffffu, u2, s0l + 2);
                v3 = __shfl_sync(0xffffffffu, u3, s0l + 2);
                pa[nt][3] = odd ? v3 : v2;
            }

            float O[4][4];
#pragma unroll
            for (int nd = 0; nd < 4; ++nd) { O[nd][0] = O[nd][1] = O[nd][2] = O[nd][3] = 0.f; }
#pragma unroll
            for (int kt = 0; kt < 8; ++kt) {
#pragma unroll
                for (int nd = 0; nd < 4; ++nd) {
                    const float* vp = vsm + (kt * 8 + ql) * QS + h * HD + nd * 8 + qr;
                    uint32_t b0 = f2tf(vp[0]);
                    uint32_t b1 = f2tf(vp[4 * QS]);
                    mma_tf32(O[nd][0], O[nd][1], O[nd][2], O[nd][3],
                             pa[kt][0], pa[kt][1], pa[kt][2], pa[kt][3], b0, b1);
                }
            }

#pragma unroll
            for (int nd = 0; nd < 4; ++nd) {
                uint2 st0, st1;
                st0.x = f2tf(O[nd][0] * inv0); st0.y = f2tf(O[nd][1] * inv0);
                st1.x = f2tf(O[nd][2] * inv1); st1.y = f2tf(O[nd][3] * inv1);
                *(uint2*)&qs[i0r * QS + h * HD + nd * 8 + 2 * ql] = st0;
                *(uint2*)&qs[(i0r + 8) * QS + h * HD + nd * 8 + 2 * ql] = st1;
            }
        }
    }
    __syncthreads();   // all O (tf32 bits) written; vsm/kss now dead

    // =========== Phase 4: output projection, store to gmem ===========
    float* og = out + (size_t)b * (NTOK * CDIM);
    ISSUE(WSRC(3, 0, 0), BUF_ADR(12));     // prefetch first proj stage
#pragma unroll
    for (int s = 0; s < 2; ++s) {
        float accP[2][4][4];
#pragma unroll
        for (int mt = 0; mt < 2; ++mt)
#pragma unroll
            for (int nt = 0; nt < 4; ++nt)
#pragma unroll
                for (int e = 0; e < 4; ++e) accP[mt][nt][e] = 0.f;

#pragma unroll
        for (int hf = 0; hf < 2; ++hf) {
            LOAD_AF_BITS(s * 128 + hf * 64);
            const int t = 12 + s * 2 + hf;
            const uint32_t* nxt = (t < 15) ? WSRC(3, (t - 11) >> 1, (t - 11) & 1)
                                           : (const uint32_t*)0;
            STAGE(nxt, BUF_ADR((t + 1) & 15), BUF_PTR(t), accP);
        }
#pragma unroll
        for (int mt = 0; mt < 2; ++mt) {
            const int rr = r0m + mt * 16 + qr;
#pragma unroll
            for (int nt = 0; nt < 4; ++nt) {
                const int c = n0 + nt * 8 + 2 * ql;
                float2 pb2 = *(const float2*)&pb[s * 128 + c];
                *(float2*)&og[rr * CDIM + s * 128 + c] =
                    make_float2(accP[mt][nt][0] + pb2.x, accP[mt][nt][1] + pb2.y);
                *(float2*)&og[(rr + 8) * CDIM + s * 128 + c] =
                    make_float2(accP[mt][nt][2] + pb2.x, accP[mt][nt][3] + pb2.y);
            }
        }
    }
}

extern "C" void kernel_launch(void* const* d_in, const int* in_sizes, int n_in,
                              void* d_out, int out_size) {
    const float* x    = (const float*)d_in[0];
    const float* mask = (const float*)d_in[1];
    const float* qw   = (const float*)d_in[2];
    const float* qb   = (const float*)d_in[3];
    const float* kw   = (const float*)d_in[4];
    const float* kb   = (const float*)d_in[5];
    const float* vw   = (const float*)d_in[6];
    const float* vb   = (const float*)d_in[7];
    const float* pw   = (const float*)d_in[8];
    const float* pb   = (const float*)d_in[9];
    const float* w1   = (const float*)d_in[10];
    const float* b1   = (const float*)d_in[11];
    const float* w2   = (const float*)d_in[12];
    const float* ls   = (const float*)d_in[13];
    const float* rpb  = (const float*)d_in[14];
    const int*   rpi  = (const int*)d_in[15];
    float* out = (float*)d_out;

    static bool inited = false;
    if (!inited) {
        cudaFuncSetAttribute(swin_block_kernel,
                             cudaFuncAttributeMaxDynamicSharedMemorySize, SMEM_BYTES);
        inited = true;
    }

    wconv_kernel<<<512, 256>>>(qw, kw, vw, pw);
    cpb_mlp_kernel<<<225, 128>>>(rpb, w1, b1, w2);
    bias_combine_kernel<<<(NWIN * NHEADS * NTOK * NTOK + 255) / 256, 256>>>(rpi, mask);
    swin_block_kernel<<<NBATCH, 256, SMEM_BYTES>>>(x, qb, kb, vb, pb, ls, out);
}